// round 4
// baseline (speedup 1.0000x reference)
#include <cuda_runtime.h>
#include <math.h>
#include <float.h>

#define NB    8192
#define GRID  128
#define NT    256
#define RPB   (NB / GRID)      // 64 rows per block
#define CHK   512
#define NCH   (NB / CHK)       // 16 sorted chunks

__device__ __align__(16) float g_risk[NB];
__device__ __align__(16) float g_e[NB];
__device__ __align__(16) float g_tsrt[NB];
__device__ __align__(16) float g_pe[NB];
__device__ float g_nll[GRID];
__device__ float g_per[GRID];
__device__ int   g_cnt[GRID];
__device__ int   g_ticket;
__device__ int   g_bar_count;
__device__ volatile int g_bar_gen;

__device__ __forceinline__ void grid_barrier() {
    __threadfence();
    __syncthreads();
    if (threadIdx.x == 0) {
        int gen = g_bar_gen;
        if (atomicAdd(&g_bar_count, 1) == GRID - 1) {
            g_bar_count = 0;
            __threadfence();
            g_bar_gen = gen + 1;
        } else {
            while (g_bar_gen == gen) { __nanosleep(32); }
        }
    }
    __syncthreads();
}

extern "C" __global__ void __launch_bounds__(NT, 1)
surv_fused_kernel(const float* __restrict__ outputs,
                  const int* __restrict__ y,
                  const float* __restrict__ t,
                  const int* __restrict__ c,
                  float* __restrict__ out)
{
    extern __shared__ float sm[];          // 64 KB dynamic
    __shared__ float redf[NT];
    __shared__ int   redi[NT];
    __shared__ int   is_last;

    const int tid = threadIdx.x;
    const int blk = blockIdx.x;
    const float EPSC = 1e-7f;

    // ================= Phase A: per-row risk / e / NLL =================
    float nll = 0.f;
    if (tid < RPB) {
        int r = blk * RPB + tid;
        float4 o4 = ((const float4*)outputs)[r];
        float o[4] = {o4.x, o4.y, o4.z, o4.w};
        float hz[4], Sc[4];
        float Sp = 1.f, Ssum = 0.f;
        #pragma unroll
        for (int k = 0; k < 4; k++) {
            float h = 1.f / (1.f + __expf(-o[k]));
            hz[k] = h;
            Sp *= (1.f - h);
            Sc[k] = Sp;
            Ssum += Sp;
        }
        float risk = -Ssum;
        int yi = y[r];
        float s_prev = fmaxf((yi == 0) ? 1.f : Sc[yi - 1], EPSC);
        float h_this = fmaxf(hz[yi], EPSC);
        float s_this = fmaxf(Sc[yi], EPSC);
        float cf = (float)c[r];
        nll = -(1.f - cf) * (__logf(s_prev) + __logf(h_this))
              - cf * __logf(s_this);
        g_risk[r] = risk;
        g_e[r]    = __expf(risk);
    }
    redf[tid] = nll;
    __syncthreads();
    for (int off = NT >> 1; off > 0; off >>= 1) {
        if (tid < off) redf[tid] += redf[tid + off];
        __syncthreads();
    }
    if (tid == 0) g_nll[blk] = redf[0];

    grid_barrier();

    // ================= Phase B: blocks 0..15 sort their chunk =================
    if (blk < NCH) {
        float* ts = sm;            // [CHK]
        float* es = sm + CHK;      // [CHK]
        #pragma unroll
        for (int u = 0; u < CHK / NT; u++) {
            int i = tid + u * NT;
            ts[i] = t[blk * CHK + i];
            es[i] = g_e[blk * CHK + i];
        }
        __syncthreads();

        // bitonic sort descending by t, carry e
        for (int k = 2; k <= CHK; k <<= 1) {
            for (int j = k >> 1; j > 0; j >>= 1) {
                #pragma unroll
                for (int u = 0; u < CHK / NT; u++) {
                    int i = tid + u * NT;
                    int l = i ^ j;
                    if (l > i) {
                        float a = ts[i], b = ts[l];
                        bool desc = ((i & k) == 0);
                        bool sw = desc ? (a < b) : (a > b);
                        if (sw) {
                            ts[i] = b; ts[l] = a;
                            float e2 = es[i]; es[i] = es[l]; es[l] = e2;
                        }
                    }
                }
                __syncthreads();
            }
        }

        // inclusive prefix sum of es (Hillis-Steele, 2 elems/thread)
        for (int off = 1; off < CHK; off <<= 1) {
            float a0 = (tid >= off) ? es[tid - off] : 0.f;
            float a1 = es[tid + NT - off];
            __syncthreads();
            es[tid]      += a0;
            es[tid + NT] += a1;
            __syncthreads();
        }

        #pragma unroll
        for (int u = 0; u < CHK / NT; u++) {
            int i = tid + u * NT;
            g_tsrt[blk * CHK + i] = ts[i];
            g_pe[blk * CHK + i]   = es[i];
        }
    }

    grid_barrier();

    // ================= Phase C: rank queries (4 threads per row) =================
    float* t_s  = sm;            // [NB]
    float* pe_s = sm + NB;       // [NB]
    #pragma unroll
    for (int i = tid; i < NB / 4; i += NT) {
        ((float4*)t_s)[i]  = ((const float4*)g_tsrt)[i];
        ((float4*)pe_s)[i] = ((const float4*)g_pe)[i];
    }

    const int row = blk * RPB + (tid >> 2);
    const int q   = tid & 3;
    const float ti = t[row];
    __syncthreads();

    // 4 interleaved binary searches over chunks w = q*4+k
    int cw[4] = {0, 0, 0, 0};
    #pragma unroll
    for (int s = CHK / 2; s > 0; s >>= 1) {
        #pragma unroll
        for (int k = 0; k < 4; k++) {
            int w = q * 4 + k;
            cw[k] += (t_s[w * CHK + cw[k] + s - 1] > ti) ? s : 0;
        }
    }
    #pragma unroll
    for (int k = 0; k < 4; k++) {
        int w = q * 4 + k;
        cw[k] += (t_s[w * CHK + cw[k]] > ti) ? 1 : 0;
    }

    float sum = 0.f;
    int   cnt = 0;
    #pragma unroll
    for (int k = 0; k < 4; k++) {
        if (cw[k] > 0) {
            sum += pe_s[(q * 4 + k) * CHK + cw[k] - 1];
            cnt += cw[k];
        }
    }
    // combine the 4 lanes of this row (lanes differ only in bits 0-1)
    sum += __shfl_xor_sync(0xffffffffu, sum, 1);
    sum += __shfl_xor_sync(0xffffffffu, sum, 2);
    cnt += __shfl_xor_sync(0xffffffffu, cnt, 1);
    cnt += __shfl_xor_sync(0xffffffffu, cnt, 2);

    float per = 0.f;
    int   cv  = 0;
    if (q == 0) {
        bool valid = (c[row] == 0) && (cnt > 0);
        if (valid) {
            per = __logf(sum) - g_risk[row];
            cv  = 1;
        }
    }
    redf[tid] = per;
    redi[tid] = cv;
    __syncthreads();
    for (int off = NT >> 1; off > 0; off >>= 1) {
        if (tid < off) {
            redf[tid] += redf[tid + off];
            redi[tid] += redi[tid + off];
        }
        __syncthreads();
    }
    if (tid == 0) {
        g_per[blk] = redf[0];
        g_cnt[blk] = redi[0];
        __threadfence();
        int tk = atomicAdd(&g_ticket, 1);
        is_last = (tk == GRID - 1) ? 1 : 0;
    }
    __syncthreads();

    // ================= Finalize: last block writes scalar =================
    if (is_last && tid == 0) {
        __threadfence();
        float per_t = 0.f, nll_t = 0.f;
        int cnt_t = 0;
        #pragma unroll 8
        for (int b = 0; b < GRID; b++) {
            per_t += g_per[b];
            cnt_t += g_cnt[b];
            nll_t += g_nll[b];
        }
        float rank = (cnt_t > 0) ? (per_t / (float)cnt_t) : 0.f;
        out[0] = nll_t / (float)NB + 0.5f * rank;
        g_ticket = 0;   // self-reset for graph replay
    }
}

extern "C" void kernel_launch(void* const* d_in, const int* in_sizes, int n_in,
                              void* d_out, int out_size)
{
    const float* outputs = (const float*)d_in[0];
    const int*   y       = (const int*)d_in[1];
    const float* t       = (const float*)d_in[2];
    const int*   c       = (const int*)d_in[3];
    float*       out     = (float*)d_out;

    size_t smem = (size_t)NB * 2 * sizeof(float);   // 64 KB
    cudaFuncSetAttribute(surv_fused_kernel,
                         cudaFuncAttributeMaxDynamicSharedMemorySize, (int)smem);
    surv_fused_kernel<<<GRID, NT, smem>>>(outputs, y, t, c, out);
}